// round 7
// baseline (speedup 1.0000x reference)
#include <cuda_runtime.h>
#include <cstdint>

// Chamfer distance, B=8, D=3, N=4096, fp32.
// R7: R4 hot loop (clean, unroll 8) + merged reduction kernel (ticket-based,
// deterministic) to cut launch overhead. Main kernel believed near the
// packed-fp32 fma-pipe wall (~57K cyc/SMSP); this round confirms/denies.

#define NN 4096
#define BB 8
#define RT 128        // source rows per block
#define CT 1024       // target cols per block = 4 warps * 256
#define NSLICE 16     // 4 coltiles * 4 warps
#define NPART 32      // rowtiles
#define RBLOCKS 64    // reduce kernel blocks

__device__ float g_rowslice[NSLICE * BB * NN];
__device__ float g_colpart[NPART * BB * NN];
__device__ double g_bsum[RBLOCKS];
__device__ unsigned g_ticket;   // harness reruns: must reset each launch

typedef unsigned long long u64;

__device__ __forceinline__ u64 pack2(float a, float b) {
    u64 r; asm("mov.b64 %0,{%1,%2};" : "=l"(r) : "f"(a), "f"(b)); return r;
}
__device__ __forceinline__ void unpack2(u64 v, float& a, float& b) {
    asm("mov.b64 {%0,%1},%2;" : "=f"(a), "=f"(b) : "l"(v));
}
__device__ __forceinline__ u64 add2(u64 a, u64 b) {
    u64 r; asm("add.rn.f32x2 %0,%1,%2;" : "=l"(r) : "l"(a), "l"(b)); return r;
}
__device__ __forceinline__ u64 fma2(u64 a, u64 b, u64 c) {
    u64 r; asm("fma.rn.f32x2 %0,%1,%2,%3;" : "=l"(r) : "l"(a), "l"(b), "l"(c)); return r;
}

__global__ void cd_zero_ticket() { if (threadIdx.x == 0) g_ticket = 0u; }

__global__ __launch_bounds__(128, 7) void cd_main_kernel(
    const float* __restrict__ srcs, const float* __restrict__ tgts) {
    __shared__ __align__(16) float smrow[RT * 8];   // (-x,-x,-y,-y)(-z,-z,hrs,hrs)
    __shared__ float spart[4][32 * 33];

    const int b    = blockIdx.z;
    const int r0   = blockIdx.y * RT;
    const int c0   = blockIdx.x * CT;
    const int tid  = threadIdx.x;
    const int w    = tid >> 5;
    const int lane = tid & 31;

    const float* sb = srcs + (size_t)b * 3 * NN;
    {
        const int i = r0 + tid;
        const float x = sb[i], y = sb[NN + i], z = sb[2 * NN + i];
        const float hrs = 0.5f * (x * x + y * y + z * z);
        float4* p = reinterpret_cast<float4*>(smrow + tid * 8);
        p[0] = make_float4(-x, -x, -y, -y);
        p[1] = make_float4(-z, -z, hrs, hrs);
    }
    __syncthreads();

    const int col0 = c0 + w * 256 + lane * 8;
    const float* tb = tgts + (size_t)b * 3 * NN;
    const float4 X0 = *reinterpret_cast<const float4*>(tb + col0);
    const float4 X1 = *reinterpret_cast<const float4*>(tb + col0 + 4);
    const float4 Y0 = *reinterpret_cast<const float4*>(tb + NN + col0);
    const float4 Y1 = *reinterpret_cast<const float4*>(tb + NN + col0 + 4);
    const float4 Z0 = *reinterpret_cast<const float4*>(tb + 2 * NN + col0);
    const float4 Z1 = *reinterpret_cast<const float4*>(tb + 2 * NN + col0 + 4);

    const u64 tx0 = pack2(X0.x, X0.y), tx1 = pack2(X0.z, X0.w);
    const u64 tx2 = pack2(X1.x, X1.y), tx3 = pack2(X1.z, X1.w);
    const u64 ty0 = pack2(Y0.x, Y0.y), ty1 = pack2(Y0.z, Y0.w);
    const u64 ty2 = pack2(Y1.x, Y1.y), ty3 = pack2(Y1.z, Y1.w);
    const u64 tz0 = pack2(Z0.x, Z0.y), tz1 = pack2(Z0.z, Z0.w);
    const u64 tz2 = pack2(Z1.x, Z1.y), tz3 = pack2(Z1.z, Z1.w);
    const u64 hrt0 = pack2(0.5f*(X0.x*X0.x + Y0.x*Y0.x + Z0.x*Z0.x),
                           0.5f*(X0.y*X0.y + Y0.y*Y0.y + Z0.y*Z0.y));
    const u64 hrt1 = pack2(0.5f*(X0.z*X0.z + Y0.z*Y0.z + Z0.z*Z0.z),
                           0.5f*(X0.w*X0.w + Y0.w*Y0.w + Z0.w*Z0.w));
    const u64 hrt2 = pack2(0.5f*(X1.x*X1.x + Y1.x*Y1.x + Z1.x*Z1.x),
                           0.5f*(X1.y*X1.y + Y1.y*Y1.y + Z1.y*Z1.y));
    const u64 hrt3 = pack2(0.5f*(X1.z*X1.z + Y1.z*Y1.z + Z1.z*Z1.z),
                           0.5f*(X1.w*X1.w + Y1.w*Y1.w + Z1.w*Z1.w));

    const float INF = __int_as_float(0x7F800000);
    float cm0 = INF, cm1 = INF, cm2 = INF, cm3 = INF;
    float cm4 = INF, cm5 = INF, cm6 = INF, cm7 = INF;

    float* myPart = &spart[w][0];
    const int slice = blockIdx.x * 4 + w;
    float* rowOut = g_rowslice + (size_t)slice * (BB * NN) + b * NN + r0;

    for (int rc = 0; rc < RT; rc += 32) {
        const float* rp = smrow + rc * 8;
        #pragma unroll 8
        for (int rr = 0; rr < 32; ++rr) {
            const ulonglong2 A  = *reinterpret_cast<const ulonglong2*>(rp + rr * 8);
            const ulonglong2 Bq = *reinterpret_cast<const ulonglong2*>(rp + rr * 8 + 4);
            u64 d0 = add2(Bq.y, hrt0);
            u64 d1 = add2(Bq.y, hrt1);
            u64 d2 = add2(Bq.y, hrt2);
            u64 d3 = add2(Bq.y, hrt3);
            d0 = fma2(A.x, tx0, d0);  d1 = fma2(A.x, tx1, d1);
            d2 = fma2(A.x, tx2, d2);  d3 = fma2(A.x, tx3, d3);
            d0 = fma2(A.y, ty0, d0);  d1 = fma2(A.y, ty1, d1);
            d2 = fma2(A.y, ty2, d2);  d3 = fma2(A.y, ty3, d3);
            d0 = fma2(Bq.x, tz0, d0); d1 = fma2(Bq.x, tz1, d1);
            d2 = fma2(Bq.x, tz2, d2); d3 = fma2(Bq.x, tz3, d3);
            float f0, f1, f2, f3, f4, f5, f6, f7;
            unpack2(d0, f0, f1); unpack2(d1, f2, f3);
            unpack2(d2, f4, f5); unpack2(d3, f6, f7);
            cm0 = fminf(cm0, f0); cm1 = fminf(cm1, f1);
            cm2 = fminf(cm2, f2); cm3 = fminf(cm3, f3);
            cm4 = fminf(cm4, f4); cm5 = fminf(cm5, f5);
            cm6 = fminf(cm6, f6); cm7 = fminf(cm7, f7);
            const float p01 = fminf(f0, f1), p23 = fminf(f2, f3);
            const float p45 = fminf(f4, f5), p67 = fminf(f6, f7);
            myPart[lane * 33 + rr] = fminf(fminf(p01, p23), fminf(p45, p67));
        }
        __syncwarp();
        float ma = myPart[lane];
        float mb = myPart[16 * 33 + lane];
        #pragma unroll
        for (int k = 1; k < 16; ++k) {
            ma = fminf(ma, myPart[k * 33 + lane]);
            mb = fminf(mb, myPart[(k + 16) * 33 + lane]);
        }
        rowOut[rc + lane] = fminf(ma, mb);
        __syncwarp();
    }

    float* cp = g_colpart + (size_t)blockIdx.y * (BB * NN) + b * NN + col0;
    *reinterpret_cast<float4*>(cp)     = make_float4(cm0, cm1, cm2, cm3);
    *reinterpret_cast<float4*>(cp + 4) = make_float4(cm4, cm5, cm6, cm7);
}

// single merged reduction: RBLOCKS blocks of 512 threads; last block (ticket)
// deterministically combines per-block partials in double and writes out.
__global__ __launch_bounds__(512) void cd_reduce_kernel(float* __restrict__ out) {
    __shared__ float swarp[16];
    __shared__ bool amLast;
    const int tid = threadIdx.x;
    const int g   = blockIdx.x * 512 + tid;   // 0..32767

    float v = g_rowslice[g];
    #pragma unroll
    for (int s = 1; s < NSLICE; ++s) v = fminf(v, g_rowslice[s * (BB * NN) + g]);
    float v2 = g_colpart[g];
    #pragma unroll
    for (int p = 1; p < NPART; ++p) v2 = fminf(v2, g_colpart[p * (BB * NN) + g]);

    float s = 2.0f * (v + v2);   // undo h = d/2 scaling
    #pragma unroll
    for (int o = 16; o; o >>= 1) s += __shfl_down_sync(0xffffffff, s, o);
    if ((tid & 31) == 0) swarp[tid >> 5] = s;
    __syncthreads();
    if (tid < 32) {
        float t = (tid < 16) ? swarp[tid] : 0.f;
        #pragma unroll
        for (int o = 8; o; o >>= 1) t += __shfl_down_sync(0xffffffff, t, o);
        if (tid == 0) {
            g_bsum[blockIdx.x] = (double)t;
            __threadfence();
            unsigned done = atomicAdd(&g_ticket, 1u);
            amLast = (done == RBLOCKS - 1);
        }
    }
    __syncthreads();
    if (amLast && tid < RBLOCKS) {
        double d = g_bsum[tid];
        #pragma unroll
        for (int o = 16; o; o >>= 1) d += __shfl_down_sync(0xffffffff, d, o);
        if ((tid & 31) == 0) swarp[tid >> 5] = (float)0;  // unused; keep smem warm
        // RBLOCKS=64 -> two warps; combine via smem
        __shared__ double dsum[2];
        if ((tid & 31) == 0) dsum[tid >> 5] = d;
        __syncwarp();
        if (tid == 0) out[0] = (float)((dsum[0] + dsum[1]) / (double)(BB * NN));
    }
}

extern "C" void kernel_launch(void* const* d_in, const int* in_sizes, int n_in,
                              void* d_out, int out_size) {
    const float* srcs = (const float*)d_in[0];
    const float* tgts = (const float*)d_in[1];
    float* out = (float*)d_out;

    cd_zero_ticket<<<1, 32>>>();
    dim3 grid(NN / CT, NN / RT, BB);  // (4, 32, 8) = 1024 blocks
    cd_main_kernel<<<grid, 128>>>(srcs, tgts);
    cd_reduce_kernel<<<RBLOCKS, 512>>>(out);
}

// round 8
// speedup vs baseline: 1.0985x; 1.0985x over previous
#include <cuda_runtime.h>
#include <cstdint>

// Chamfer distance, B=8, D=3, N=4096, fp32.
// R8: two launches only (self-resetting ticket in reduce kernel);
// RT=64 -> 2048 blocks + launch_bounds(128,8) for higher resident warps.

#define NN 4096
#define BB 8
#define RT 64         // source rows per block
#define CT 1024       // target cols per block = 4 warps * 256
#define NSLICE 16     // 4 coltiles * 4 warps
#define NPART 64      // rowtiles
#define RBLOCKS 64    // reduce kernel blocks

__device__ float g_rowslice[NSLICE * BB * NN];
__device__ float g_colpart[NPART * BB * NN];
__device__ double g_bsum[RBLOCKS];
__device__ unsigned g_ticket;   // zero-init; last reduce block resets to 0

typedef unsigned long long u64;

__device__ __forceinline__ u64 pack2(float a, float b) {
    u64 r; asm("mov.b64 %0,{%1,%2};" : "=l"(r) : "f"(a), "f"(b)); return r;
}
__device__ __forceinline__ void unpack2(u64 v, float& a, float& b) {
    asm("mov.b64 {%0,%1},%2;" : "=f"(a), "=f"(b) : "l"(v));
}
__device__ __forceinline__ u64 add2(u64 a, u64 b) {
    u64 r; asm("add.rn.f32x2 %0,%1,%2;" : "=l"(r) : "l"(a), "l"(b)); return r;
}
__device__ __forceinline__ u64 fma2(u64 a, u64 b, u64 c) {
    u64 r; asm("fma.rn.f32x2 %0,%1,%2,%3;" : "=l"(r) : "l"(a), "l"(b), "l"(c)); return r;
}

__global__ __launch_bounds__(128, 8) void cd_main_kernel(
    const float* __restrict__ srcs, const float* __restrict__ tgts) {
    __shared__ __align__(16) float smrow[RT * 8];   // (-x,-x,-y,-y)(-z,-z,hrs,hrs)
    __shared__ float spart[4][32 * 33];

    const int b    = blockIdx.z;
    const int r0   = blockIdx.y * RT;
    const int c0   = blockIdx.x * CT;
    const int tid  = threadIdx.x;
    const int w    = tid >> 5;
    const int lane = tid & 31;

    const float* sb = srcs + (size_t)b * 3 * NN;
    if (tid < RT) {
        const int i = r0 + tid;
        const float x = sb[i], y = sb[NN + i], z = sb[2 * NN + i];
        const float hrs = 0.5f * (x * x + y * y + z * z);
        float4* p = reinterpret_cast<float4*>(smrow + tid * 8);
        p[0] = make_float4(-x, -x, -y, -y);
        p[1] = make_float4(-z, -z, hrs, hrs);
    }
    __syncthreads();

    const int col0 = c0 + w * 256 + lane * 8;
    const float* tb = tgts + (size_t)b * 3 * NN;
    const float4 X0 = *reinterpret_cast<const float4*>(tb + col0);
    const float4 X1 = *reinterpret_cast<const float4*>(tb + col0 + 4);
    const float4 Y0 = *reinterpret_cast<const float4*>(tb + NN + col0);
    const float4 Y1 = *reinterpret_cast<const float4*>(tb + NN + col0 + 4);
    const float4 Z0 = *reinterpret_cast<const float4*>(tb + 2 * NN + col0);
    const float4 Z1 = *reinterpret_cast<const float4*>(tb + 2 * NN + col0 + 4);

    const u64 tx0 = pack2(X0.x, X0.y), tx1 = pack2(X0.z, X0.w);
    const u64 tx2 = pack2(X1.x, X1.y), tx3 = pack2(X1.z, X1.w);
    const u64 ty0 = pack2(Y0.x, Y0.y), ty1 = pack2(Y0.z, Y0.w);
    const u64 ty2 = pack2(Y1.x, Y1.y), ty3 = pack2(Y1.z, Y1.w);
    const u64 tz0 = pack2(Z0.x, Z0.y), tz1 = pack2(Z0.z, Z0.w);
    const u64 tz2 = pack2(Z1.x, Z1.y), tz3 = pack2(Z1.z, Z1.w);
    const u64 hrt0 = pack2(0.5f*(X0.x*X0.x + Y0.x*Y0.x + Z0.x*Z0.x),
                           0.5f*(X0.y*X0.y + Y0.y*Y0.y + Z0.y*Z0.y));
    const u64 hrt1 = pack2(0.5f*(X0.z*X0.z + Y0.z*Y0.z + Z0.z*Z0.z),
                           0.5f*(X0.w*X0.w + Y0.w*Y0.w + Z0.w*Z0.w));
    const u64 hrt2 = pack2(0.5f*(X1.x*X1.x + Y1.x*Y1.x + Z1.x*Z1.x),
                           0.5f*(X1.y*X1.y + Y1.y*Y1.y + Z1.y*Z1.y));
    const u64 hrt3 = pack2(0.5f*(X1.z*X1.z + Y1.z*Y1.z + Z1.z*Z1.z),
                           0.5f*(X1.w*X1.w + Y1.w*Y1.w + Z1.w*Z1.w));

    const float INF = __int_as_float(0x7F800000);
    float cm0 = INF, cm1 = INF, cm2 = INF, cm3 = INF;
    float cm4 = INF, cm5 = INF, cm6 = INF, cm7 = INF;

    float* myPart = &spart[w][0];
    const int slice = blockIdx.x * 4 + w;
    float* rowOut = g_rowslice + (size_t)slice * (BB * NN) + b * NN + r0;

    for (int rc = 0; rc < RT; rc += 32) {
        const float* rp = smrow + rc * 8;
        #pragma unroll 8
        for (int rr = 0; rr < 32; ++rr) {
            const ulonglong2 A  = *reinterpret_cast<const ulonglong2*>(rp + rr * 8);
            const ulonglong2 Bq = *reinterpret_cast<const ulonglong2*>(rp + rr * 8 + 4);
            u64 d0 = add2(Bq.y, hrt0);
            u64 d1 = add2(Bq.y, hrt1);
            u64 d2 = add2(Bq.y, hrt2);
            u64 d3 = add2(Bq.y, hrt3);
            d0 = fma2(A.x, tx0, d0);  d1 = fma2(A.x, tx1, d1);
            d2 = fma2(A.x, tx2, d2);  d3 = fma2(A.x, tx3, d3);
            d0 = fma2(A.y, ty0, d0);  d1 = fma2(A.y, ty1, d1);
            d2 = fma2(A.y, ty2, d2);  d3 = fma2(A.y, ty3, d3);
            d0 = fma2(Bq.x, tz0, d0); d1 = fma2(Bq.x, tz1, d1);
            d2 = fma2(Bq.x, tz2, d2); d3 = fma2(Bq.x, tz3, d3);
            float f0, f1, f2, f3, f4, f5, f6, f7;
            unpack2(d0, f0, f1); unpack2(d1, f2, f3);
            unpack2(d2, f4, f5); unpack2(d3, f6, f7);
            cm0 = fminf(cm0, f0); cm1 = fminf(cm1, f1);
            cm2 = fminf(cm2, f2); cm3 = fminf(cm3, f3);
            cm4 = fminf(cm4, f4); cm5 = fminf(cm5, f5);
            cm6 = fminf(cm6, f6); cm7 = fminf(cm7, f7);
            const float p01 = fminf(f0, f1), p23 = fminf(f2, f3);
            const float p45 = fminf(f4, f5), p67 = fminf(f6, f7);
            myPart[lane * 33 + rr] = fminf(fminf(p01, p23), fminf(p45, p67));
        }
        __syncwarp();
        float ma = myPart[lane];
        float mb = myPart[16 * 33 + lane];
        #pragma unroll
        for (int k = 1; k < 16; ++k) {
            ma = fminf(ma, myPart[k * 33 + lane]);
            mb = fminf(mb, myPart[(k + 16) * 33 + lane]);
        }
        rowOut[rc + lane] = fminf(ma, mb);
        __syncwarp();
    }

    float* cp = g_colpart + (size_t)blockIdx.y * (BB * NN) + b * NN + col0;
    *reinterpret_cast<float4*>(cp)     = make_float4(cm0, cm1, cm2, cm3);
    *reinterpret_cast<float4*>(cp + 4) = make_float4(cm4, cm5, cm6, cm7);
}

// merged reduction, self-resetting ticket (last block resets g_ticket to 0).
__global__ __launch_bounds__(512) void cd_reduce_kernel(float* __restrict__ out) {
    __shared__ float swarp[16];
    __shared__ double dsum[2];
    __shared__ bool amLast;
    const int tid = threadIdx.x;
    const int g   = blockIdx.x * 512 + tid;   // 0..32767

    float v = g_rowslice[g];
    #pragma unroll
    for (int s = 1; s < NSLICE; ++s) v = fminf(v, g_rowslice[s * (BB * NN) + g]);
    // 4 independent chains over the 64 col parts
    float a = g_colpart[g];
    float bq = g_colpart[1 * (BB * NN) + g];
    float c = g_colpart[2 * (BB * NN) + g];
    float d = g_colpart[3 * (BB * NN) + g];
    #pragma unroll
    for (int p = 4; p < NPART; p += 4) {
        a  = fminf(a,  g_colpart[(p + 0) * (BB * NN) + g]);
        bq = fminf(bq, g_colpart[(p + 1) * (BB * NN) + g]);
        c  = fminf(c,  g_colpart[(p + 2) * (BB * NN) + g]);
        d  = fminf(d,  g_colpart[(p + 3) * (BB * NN) + g]);
    }
    float v2 = fminf(fminf(a, bq), fminf(c, d));

    float s = 2.0f * (v + v2);   // undo h = d/2 scaling
    #pragma unroll
    for (int o = 16; o; o >>= 1) s += __shfl_down_sync(0xffffffff, s, o);
    if ((tid & 31) == 0) swarp[tid >> 5] = s;
    __syncthreads();
    if (tid < 32) {
        float t = (tid < 16) ? swarp[tid] : 0.f;
        #pragma unroll
        for (int o = 8; o; o >>= 1) t += __shfl_down_sync(0xffffffff, t, o);
        if (tid == 0) {
            g_bsum[blockIdx.x] = (double)t;
            __threadfence();
            unsigned done = atomicAdd(&g_ticket, 1u);
            amLast = (done == RBLOCKS - 1);
        }
    }
    __syncthreads();
    if (amLast) {
        if (tid < RBLOCKS) {
            double dd = g_bsum[tid];
            #pragma unroll
            for (int o = 16; o; o >>= 1) dd += __shfl_down_sync(0xffffffff, dd, o);
            if ((tid & 31) == 0) dsum[tid >> 5] = dd;
        }
        __syncthreads();
        if (tid == 0) {
            out[0] = (float)((dsum[0] + dsum[1]) / (double)(BB * NN));
            g_ticket = 0u;   // reset for next graph replay
        }
    }
}

extern "C" void kernel_launch(void* const* d_in, const int* in_sizes, int n_in,
                              void* d_out, int out_size) {
    const float* srcs = (const float*)d_in[0];
    const float* tgts = (const float*)d_in[1];
    float* out = (float*)d_out;

    dim3 grid(NN / CT, NN / RT, BB);  // (4, 64, 8) = 2048 blocks
    cd_main_kernel<<<grid, 128>>>(srcs, tgts);
    cd_reduce_kernel<<<RBLOCKS, 512>>>(out);
}